// round 1
// baseline (speedup 1.0000x reference)
#include <cuda_runtime.h>
#include <math.h>

#define LQ 2048
#define DD 1024
#define NH 16
#define DHD 64
#define TI 16
#define CJ 64
#define KSTR 65

// scratch (static device allocations are allowed)
__device__ float g_h [LQ*DD];
__device__ float g_q [NH*LQ*DHD];
__device__ float g_k [NH*LQ*DHD];
__device__ float g_v [NH*LQ*DHD];
__device__ float g_o [LQ*DD];
__device__ float g_yo[LQ*DD];
__device__ float g_gg[LQ*DD];

// ---------------- LayerNorm ----------------
__global__ void ln_kernel(const float* __restrict__ x,
                          const float* __restrict__ gamma,
                          const float* __restrict__ beta) {
    __shared__ float red[8];
    int row = blockIdx.x;
    int t = threadIdx.x;
    const float* xr = x + (size_t)row * DD;
    float v[4];
    float s = 0.f;
#pragma unroll
    for (int i = 0; i < 4; i++) { v[i] = xr[t + 256*i]; s += v[i]; }
#pragma unroll
    for (int o = 16; o; o >>= 1) s += __shfl_xor_sync(0xffffffffu, s, o);
    if ((t & 31) == 0) red[t >> 5] = s;
    __syncthreads();
    float tot = 0.f;
#pragma unroll
    for (int w = 0; w < 8; w++) tot += red[w];
    float mean = tot * (1.f / DD);
    __syncthreads();
    float s2 = 0.f;
#pragma unroll
    for (int i = 0; i < 4; i++) { float d = v[i] - mean; s2 += d*d; }
#pragma unroll
    for (int o = 16; o; o >>= 1) s2 += __shfl_xor_sync(0xffffffffu, s2, o);
    if ((t & 31) == 0) red[t >> 5] = s2;
    __syncthreads();
    float tot2 = 0.f;
#pragma unroll
    for (int w = 0; w < 8; w++) tot2 += red[w];
    float inv = rsqrtf(tot2 * (1.f / DD) + 1e-5f);
#pragma unroll
    for (int i = 0; i < 4; i++) {
        int c = t + 256*i;
        g_h[(size_t)row*DD + c] = (v[i] - mean) * inv * gamma[c] + beta[c];
    }
}

// ---------------- SGEMM 128x128x8, C = A(2048x1024) @ B(1024x1024) ----------------
// mode 0: C[m*1024+n]   mode 1: head-major C[((n>>6)*LQ + m)*64 + (n&63)]
__global__ void __launch_bounds__(256)
sgemm_kernel(const float* __restrict__ A, const float* __restrict__ B,
             float* __restrict__ C, int mode) {
    __shared__ float As[8][128];
    __shared__ float Bs[8][128];
    int t = threadIdx.x;
    int bm = blockIdx.y * 128, bn = blockIdx.x * 128;
    int tx = t & 15, ty = t >> 4;
    float acc[8][8];
#pragma unroll
    for (int i = 0; i < 8; i++)
#pragma unroll
        for (int j = 0; j < 8; j++) acc[i][j] = 0.f;

    int arow = t >> 1, acol = (t & 1) * 4;
    int brow = t >> 5, bcol = (t & 31) * 4;

    for (int k0 = 0; k0 < 1024; k0 += 8) {
        float4 av = *(const float4*)&A[(size_t)(bm + arow)*1024 + k0 + acol];
        float4 bv = *(const float4*)&B[(size_t)(k0 + brow)*1024 + bn + bcol];
        As[acol+0][arow] = av.x; As[acol+1][arow] = av.y;
        As[acol+2][arow] = av.z; As[acol+3][arow] = av.w;
        *(float4*)&Bs[brow][bcol] = bv;
        __syncthreads();
#pragma unroll
        for (int k = 0; k < 8; k++) {
            float a[8], b[8];
#pragma unroll
            for (int i = 0; i < 8; i++) a[i] = As[k][ty*8 + i];
#pragma unroll
            for (int j = 0; j < 8; j++) b[j] = Bs[k][tx*8 + j];
#pragma unroll
            for (int i = 0; i < 8; i++)
#pragma unroll
                for (int j = 0; j < 8; j++)
                    acc[i][j] += a[i] * b[j];
        }
        __syncthreads();
    }
#pragma unroll
    for (int i = 0; i < 8; i++) {
        int m = bm + ty*8 + i;
#pragma unroll
        for (int j = 0; j < 8; j++) {
            int n = bn + tx*8 + j;
            if (mode == 0) {
                C[(size_t)m*1024 + n] = acc[i][j];
            } else {
                C[((size_t)(n >> 6)*LQ + m)*DHD + (n & 63)] = acc[i][j];
            }
        }
    }
}

// ---------------- RoPE on q,k,v (first 16 dims of each head) ----------------
__global__ void rope_kernel() {
    int idx = blockIdx.x * blockDim.x + threadIdx.x;   // NH*LQ*8
    int pair = idx & 7;
    int rest = idx >> 3;                               // h*LQ + l
    int l = rest & (LQ - 1);
    int base = rest * DHD;
    float invf = powf(10000.f, -(float)pair * 0.125f);
    float ang = (float)l * invf;
    float s, c;
    sincosf(ang, &s, &c);
    float a, b;
    a = g_q[base + pair]; b = g_q[base + pair + 8];
    g_q[base + pair] = a*c - b*s; g_q[base + pair + 8] = b*c + a*s;
    a = g_k[base + pair]; b = g_k[base + pair + 8];
    g_k[base + pair] = a*c - b*s; g_k[base + pair + 8] = b*c + a*s;
    a = g_v[base + pair]; b = g_v[base + pair + 8];
    g_v[base + pair] = a*c - b*s; g_v[base + pair + 8] = b*c + a*s;
}

// ---------------- fused attention: dots + softmax + attn_map + AV ----------------
// one CTA per (head, 16-row tile); full 16x2048 score tile kept in smem
__global__ void __launch_bounds__(256)
attn_kernel(const float* __restrict__ prev,
            float* __restrict__ dots, float* __restrict__ attn) {
    extern __shared__ float sm[];
    float* Ssm = sm;                       // TI*LQ
    float* Kc  = sm + TI*LQ;               // CJ*KSTR (also reused for V)
    float* Qs  = Kc + CJ*KSTR;             // TI*KSTR
    float* red = Qs + TI*KSTR;             // 8

    int t = threadIdx.x;
    int h = blockIdx.y;
    int i0 = blockIdx.x * TI;
    const float* qh = g_q + (size_t)h*LQ*DHD;
    const float* kh = g_k + (size_t)h*LQ*DHD;
    const float* vh = g_v + (size_t)h*LQ*DHD;
    float slope = exp2f(-0.5f * (float)(h + 1));

    for (int idx = t; idx < TI*DHD; idx += 256) {
        int r = idx >> 6, d = idx & 63;
        Qs[r*KSTR + d] = qh[(size_t)(i0 + r)*DHD + d];
    }

    // ---- phase 1: S = q@k^T * scale + prev + alibi/causal, write dots ----
    int jj = t & 63;
    int rbase = (t >> 6) * 4;              // warp-uniform
    for (int jc = 0; jc < LQ; jc += CJ) {
        __syncthreads();
        for (int idx = t; idx < CJ*DHD; idx += 256) {
            int r = idx >> 6, d = idx & 63;
            Kc[r*KSTR + d] = kh[(size_t)(jc + r)*DHD + d];
        }
        __syncthreads();
        float acc0 = 0.f, acc1 = 0.f, acc2 = 0.f, acc3 = 0.f;
#pragma unroll 8
        for (int d = 0; d < DHD; d++) {
            float kv = Kc[jj*KSTR + d];
            acc0 += Qs[(rbase+0)*KSTR + d] * kv;
            acc1 += Qs[(rbase+1)*KSTR + d] * kv;
            acc2 += Qs[(rbase+2)*KSTR + d] * kv;
            acc3 += Qs[(rbase+3)*KSTR + d] * kv;
        }
        int j = jc + jj;
        float accs[4] = {acc0, acc1, acc2, acc3};
#pragma unroll
        for (int r = 0; r < 4; r++) {
            int i = i0 + rbase + r;
            int rel = i - j;
            float bias = (rel >= 0) ? (-slope * (float)rel) : -1000000000.0f;
            size_t gi = ((size_t)(h*LQ + i))*LQ + j;
            float dv = accs[r] * 0.125f + prev[gi] + bias;
            Ssm[(rbase + r)*LQ + j] = dv;
            dots[gi] = dv;
        }
    }
    __syncthreads();

    // ---- phase 1b: softmax per row; Ssm becomes attn probabilities ----
    for (int r = 0; r < TI; r++) {
        float* Sr = Ssm + r*LQ;
        float m = -3.4e38f;
        for (int j = t; j < LQ; j += 256) m = fmaxf(m, Sr[j]);
#pragma unroll
        for (int o = 16; o; o >>= 1) m = fmaxf(m, __shfl_xor_sync(0xffffffffu, m, o));
        if ((t & 31) == 0) red[t >> 5] = m;
        __syncthreads();
        float mm = red[0];
#pragma unroll
        for (int w = 1; w < 8; w++) mm = fmaxf(mm, red[w]);
        __syncthreads();
        float ssum = 0.f;
        for (int j = t; j < LQ; j += 256) {
            float e = __expf(Sr[j] - mm);
            Sr[j] = e;
            ssum += e;
        }
#pragma unroll
        for (int o = 16; o; o >>= 1) ssum += __shfl_xor_sync(0xffffffffu, ssum, o);
        if ((t & 31) == 0) red[t >> 5] = ssum;
        __syncthreads();
        float tot = 0.f;
#pragma unroll
        for (int w = 0; w < 8; w++) tot += red[w];
        float invs = 1.f / tot;
        __syncthreads();
        size_t gbase = ((size_t)(h*LQ + i0 + r))*LQ;
        for (int j = t; j < LQ; j += 256) {
            float p = Sr[j] * invs;
            Sr[j] = p;
            attn[gbase + j] = p;
        }
    }
    __syncthreads();

    // ---- phase 2: o = attn @ v (skip fully-masked chunks; masked p == 0) ----
    int r2 = t >> 4;
    int d0 = (t & 15) * 4;
    float a0 = 0.f, a1 = 0.f, a2 = 0.f, a3 = 0.f;
    int imax = i0 + TI - 1;
    for (int jc = 0; jc <= imax; jc += CJ) {
        __syncthreads();
        for (int idx = t; idx < CJ*DHD; idx += 256) {
            int rr = idx >> 6, d = idx & 63;
            Kc[rr*KSTR + d] = vh[(size_t)(jc + rr)*DHD + d];
        }
        __syncthreads();
        const float* Sr = Ssm + (size_t)r2*LQ + jc;
#pragma unroll 8
        for (int q = 0; q < CJ; q++) {
            float p = Sr[q];
            const float* vr = Kc + q*KSTR + d0;
            a0 += p * vr[0]; a1 += p * vr[1]; a2 += p * vr[2]; a3 += p * vr[3];
        }
    }
    size_t ob = (size_t)(i0 + r2)*DD + h*DHD + d0;
    g_o[ob+0] = a0; g_o[ob+1] = a1; g_o[ob+2] = a2; g_o[ob+3] = a3;
}

// ---------------- final: y = sigmoid(x@Wg+bg) * (o@Wo+bo) + x ----------------
__global__ void final_kernel(const float* __restrict__ x,
                             const float* __restrict__ bo,
                             const float* __restrict__ bg,
                             float* __restrict__ y) {
    int idx = blockIdx.x * 256 + threadIdx.x;
    int n = idx & (DD - 1);
    float yo = g_yo[idx] + bo[n];
    float gg = g_gg[idx] + bg[n];
    float gate = 1.f / (1.f + __expf(-gg));
    y[idx] = gate * yo + x[idx];
}

extern "C" void kernel_launch(void* const* d_in, const int* in_sizes, int n_in,
                              void* d_out, int out_size) {
    const float* x     = (const float*)d_in[0];
    const float* prev  = (const float*)d_in[1];
    const float* Wq    = (const float*)d_in[2];
    const float* Wk    = (const float*)d_in[3];
    const float* Wv    = (const float*)d_in[4];
    const float* Wo    = (const float*)d_in[5];
    const float* bo    = (const float*)d_in[6];
    const float* gamma = (const float*)d_in[7];
    const float* beta  = (const float*)d_in[8];
    const float* Wg    = (const float*)d_in[9];
    const float* bg    = (const float*)d_in[10];

    float* y    = (float*)d_out;
    float* attn = y + (size_t)LQ * DD;
    float* dots = attn + (size_t)NH * LQ * LQ;

    float *ph, *pq, *pk, *pv, *po, *pyo, *pgg;
    cudaGetSymbolAddress((void**)&ph,  g_h);
    cudaGetSymbolAddress((void**)&pq,  g_q);
    cudaGetSymbolAddress((void**)&pk,  g_k);
    cudaGetSymbolAddress((void**)&pv,  g_v);
    cudaGetSymbolAddress((void**)&po,  g_o);
    cudaGetSymbolAddress((void**)&pyo, g_yo);
    cudaGetSymbolAddress((void**)&pgg, g_gg);

    size_t smb = (size_t)(TI*LQ + CJ*KSTR + TI*KSTR + 8) * sizeof(float);
    cudaFuncSetAttribute(attn_kernel, cudaFuncAttributeMaxDynamicSharedMemorySize, (int)smb);

    ln_kernel<<<LQ, 256>>>(x, gamma, beta);

    dim3 gg2(8, 16);
    sgemm_kernel<<<gg2, 256>>>(ph, Wq, pq, 1);
    sgemm_kernel<<<gg2, 256>>>(ph, Wk, pk, 1);
    sgemm_kernel<<<gg2, 256>>>(ph, Wv, pv, 1);

    rope_kernel<<<(NH*LQ*8)/256, 256>>>();

    attn_kernel<<<dim3(LQ/TI, NH), 256, smb>>>(prev, dots, attn);

    sgemm_kernel<<<gg2, 256>>>(po, Wo, pyo, 0);
    sgemm_kernel<<<gg2, 256>>>(x,  Wg, pgg, 0);

    final_kernel<<<(LQ*DD)/256, 256>>>(x, bo, bg, y);
}

// round 3
// speedup vs baseline: 2.3705x; 2.3705x over previous
#include <cuda_runtime.h>
#include <math.h>

#define LQ 2048
#define DD 1024
#define NH 16
#define DHD 64

// scratch (static device allocations are allowed)
__device__ float g_h [LQ*DD];
__device__ float g_q [NH*LQ*DHD];
__device__ float g_k [NH*LQ*DHD];
__device__ float g_v [NH*LQ*DHD];
__device__ float g_o [LQ*DD];
__device__ float g_yo[LQ*DD];
__device__ float g_gg[LQ*DD];

// ---------------- LayerNorm ----------------
__global__ void ln_kernel(const float* __restrict__ x,
                          const float* __restrict__ gamma,
                          const float* __restrict__ beta) {
    __shared__ float red[8];
    int row = blockIdx.x;
    int t = threadIdx.x;
    const float* xr = x + (size_t)row * DD;
    float v[4];
    float s = 0.f;
#pragma unroll
    for (int i = 0; i < 4; i++) { v[i] = xr[t + 256*i]; s += v[i]; }
#pragma unroll
    for (int o = 16; o; o >>= 1) s += __shfl_xor_sync(0xffffffffu, s, o);
    if ((t & 31) == 0) red[t >> 5] = s;
    __syncthreads();
    float tot = 0.f;
#pragma unroll
    for (int w = 0; w < 8; w++) tot += red[w];
    float mean = tot * (1.f / DD);
    __syncthreads();
    float s2 = 0.f;
#pragma unroll
    for (int i = 0; i < 4; i++) { float d = v[i] - mean; s2 += d*d; }
#pragma unroll
    for (int o = 16; o; o >>= 1) s2 += __shfl_xor_sync(0xffffffffu, s2, o);
    if ((t & 31) == 0) red[t >> 5] = s2;
    __syncthreads();
    float tot2 = 0.f;
#pragma unroll
    for (int w = 0; w < 8; w++) tot2 += red[w];
    float inv = rsqrtf(tot2 * (1.f / DD) + 1e-5f);
#pragma unroll
    for (int i = 0; i < 4; i++) {
        int c = t + 256*i;
        g_h[(size_t)row*DD + c] = (v[i] - mean) * inv * gamma[c] + beta[c];
    }
}

// ---------------- SGEMM 128x128x8 double-buffered ----------------
// mode 0: C[m*1024+n]   mode 1: head-major C[((n>>6)*LQ + m)*64 + (n&63)]
__global__ void __launch_bounds__(256)
sgemm_kernel(const float* __restrict__ A, const float* __restrict__ B,
             float* __restrict__ C, int mode) {
    __shared__ float As[2][8][128];
    __shared__ float Bs[2][8][128];
    int t = threadIdx.x;
    int bm = blockIdx.y * 128, bn = blockIdx.x * 128;
    int tx = t & 15, ty = t >> 4;
    int arow = t >> 1, acol = (t & 1) * 4;
    int brow = t >> 5, bcol = (t & 31) * 4;
    const float* Ap = A + (size_t)(bm + arow)*1024 + acol;
    const float* Bp = B + (size_t)brow*1024 + bn + bcol;

    float4 av = *(const float4*)Ap;
    float4 bv = *(const float4*)Bp;
    As[0][acol+0][arow] = av.x; As[0][acol+1][arow] = av.y;
    As[0][acol+2][arow] = av.z; As[0][acol+3][arow] = av.w;
    *(float4*)&Bs[0][brow][bcol] = bv;
    __syncthreads();

    float acc[8][8];
#pragma unroll
    for (int i = 0; i < 8; i++)
#pragma unroll
        for (int j = 0; j < 8; j++) acc[i][j] = 0.f;

    int buf = 0;
    for (int k0 = 8; k0 < 1024; k0 += 8) {
        av = *(const float4*)(Ap + k0);
        bv = *(const float4*)(Bp + (size_t)k0*1024);
#pragma unroll
        for (int k = 0; k < 8; k++) {
            float a[8], b[8];
            *(float4*)(a)   = *(const float4*)&As[buf][k][ty*8];
            *(float4*)(a+4) = *(const float4*)&As[buf][k][ty*8+4];
            *(float4*)(b)   = *(const float4*)&Bs[buf][k][tx*8];
            *(float4*)(b+4) = *(const float4*)&Bs[buf][k][tx*8+4];
#pragma unroll
            for (int i = 0; i < 8; i++)
#pragma unroll
                for (int j = 0; j < 8; j++)
                    acc[i][j] += a[i] * b[j];
        }
        buf ^= 1;
        As[buf][acol+0][arow] = av.x; As[buf][acol+1][arow] = av.y;
        As[buf][acol+2][arow] = av.z; As[buf][acol+3][arow] = av.w;
        *(float4*)&Bs[buf][brow][bcol] = bv;
        __syncthreads();
    }
#pragma unroll
    for (int k = 0; k < 8; k++) {
        float a[8], b[8];
        *(float4*)(a)   = *(const float4*)&As[buf][k][ty*8];
        *(float4*)(a+4) = *(const float4*)&As[buf][k][ty*8+4];
        *(float4*)(b)   = *(const float4*)&Bs[buf][k][tx*8];
        *(float4*)(b+4) = *(const float4*)&Bs[buf][k][tx*8+4];
#pragma unroll
        for (int i = 0; i < 8; i++)
#pragma unroll
            for (int j = 0; j < 8; j++)
                acc[i][j] += a[i] * b[j];
    }

#pragma unroll
    for (int i = 0; i < 8; i++) {
        int m = bm + ty*8 + i;
#pragma unroll
        for (int j = 0; j < 8; j++) {
            int n = bn + tx*8 + j;
            if (mode == 0) {
                C[(size_t)m*1024 + n] = acc[i][j];
            } else {
                C[((size_t)(n >> 6)*LQ + m)*DHD + (n & 63)] = acc[i][j];
            }
        }
    }
}

// ---------------- RoPE on q,k,v ----------------
__global__ void rope_kernel() {
    int idx = blockIdx.x * blockDim.x + threadIdx.x;   // NH*LQ*8
    int pair = idx & 7;
    int rest = idx >> 3;
    int l = rest & (LQ - 1);
    int base = rest * DHD;
    float invf = powf(10000.f, -(float)pair * 0.125f);
    float ang = (float)l * invf;
    float s, c;
    sincosf(ang, &s, &c);
    float a, b;
    a = g_q[base + pair]; b = g_q[base + pair + 8];
    g_q[base + pair] = a*c - b*s; g_q[base + pair + 8] = b*c + a*s;
    a = g_k[base + pair]; b = g_k[base + pair + 8];
    g_k[base + pair] = a*c - b*s; g_k[base + pair + 8] = b*c + a*s;
    a = g_v[base + pair]; b = g_v[base + pair + 8];
    g_v[base + pair] = a*c - b*s; g_v[base + pair + 8] = b*c + a*s;
}

// ---------------- QK: dots = q@k^T*scale + prev + alibi/causal ----------------
// 128x128 output tile, K-depth 64, register 8x8 microtile.
#define QKP 132
__global__ void __launch_bounds__(256)
qk_kernel(const float* __restrict__ prev, float* __restrict__ dots) {
    extern __shared__ float sm[];
    float* Qt = sm;              // [64][QKP] transposed: Qt[d][i]
    float* Kt = sm + 64*QKP;     // [64][QKP]
    int t = threadIdx.x;
    int h = blockIdx.z;
    int i0 = blockIdx.y * 128, j0 = blockIdx.x * 128;
    const float* qh = g_q + (size_t)h*LQ*DHD;
    const float* kh = g_k + (size_t)h*LQ*DHD;

    int lr = t >> 1;            // 0..127
    int ld0 = (t & 1) * 32;
    const float* qrow = qh + (size_t)(i0 + lr)*DHD + ld0;
    const float* krow = kh + (size_t)(j0 + lr)*DHD + ld0;
#pragma unroll
    for (int c = 0; c < 8; c++) {
        float4 v = *(const float4*)(qrow + c*4);
        Qt[(ld0 + c*4 + 0)*QKP + lr] = v.x;
        Qt[(ld0 + c*4 + 1)*QKP + lr] = v.y;
        Qt[(ld0 + c*4 + 2)*QKP + lr] = v.z;
        Qt[(ld0 + c*4 + 3)*QKP + lr] = v.w;
        float4 w = *(const float4*)(krow + c*4);
        Kt[(ld0 + c*4 + 0)*QKP + lr] = w.x;
        Kt[(ld0 + c*4 + 1)*QKP + lr] = w.y;
        Kt[(ld0 + c*4 + 2)*QKP + lr] = w.z;
        Kt[(ld0 + c*4 + 3)*QKP + lr] = w.w;
    }
    __syncthreads();

    int tx = t & 15, ty = t >> 4;
    float acc[8][8];
#pragma unroll
    for (int i = 0; i < 8; i++)
#pragma unroll
        for (int j = 0; j < 8; j++) acc[i][j] = 0.f;

#pragma unroll 8
    for (int d = 0; d < 64; d++) {
        float a[8], b[8];
        *(float4*)(a)   = *(const float4*)&Qt[d*QKP + ty*8];
        *(float4*)(a+4) = *(const float4*)&Qt[d*QKP + ty*8+4];
        *(float4*)(b)   = *(const float4*)&Kt[d*QKP + tx*8];
        *(float4*)(b+4) = *(const float4*)&Kt[d*QKP + tx*8+4];
#pragma unroll
        for (int i = 0; i < 8; i++)
#pragma unroll
            for (int j = 0; j < 8; j++)
                acc[i][j] += a[i] * b[j];
    }

    float slope = exp2f(-0.5f * (float)(h + 1));
#pragma unroll
    for (int i = 0; i < 8; i++) {
        int gi = i0 + ty*8 + i;
        size_t rowb = ((size_t)(h*LQ + gi))*LQ;
#pragma unroll
        for (int jg = 0; jg < 2; jg++) {
            int j = j0 + tx*8 + jg*4;
            float4 pv = *(const float4*)&prev[rowb + j];
            float4 ov;
            int rel;
            rel = gi - (j+0); ov.x = acc[i][jg*4+0]*0.125f + pv.x + ((rel >= 0) ? (-slope*(float)rel) : -1000000000.0f);
            rel = gi - (j+1); ov.y = acc[i][jg*4+1]*0.125f + pv.y + ((rel >= 0) ? (-slope*(float)rel) : -1000000000.0f);
            rel = gi - (j+2); ov.z = acc[i][jg*4+2]*0.125f + pv.z + ((rel >= 0) ? (-slope*(float)rel) : -1000000000.0f);
            rel = gi - (j+3); ov.w = acc[i][jg*4+3]*0.125f + pv.w + ((rel >= 0) ? (-slope*(float)rel) : -1000000000.0f);
            *(float4*)&dots[rowb + j] = ov;
        }
    }
}

// ---------------- softmax per row ----------------
__global__ void __launch_bounds__(256)
softmax_kernel(const float* __restrict__ dots, float* __restrict__ attn) {
    __shared__ float red[8];
    size_t base = (size_t)blockIdx.x * LQ;
    int t = threadIdx.x;
    float4 v0 = *(const float4*)&dots[base + t*4];
    float4 v1 = *(const float4*)&dots[base + 1024 + t*4];
    float m = fmaxf(fmaxf(fmaxf(v0.x, v0.y), fmaxf(v0.z, v0.w)),
                    fmaxf(fmaxf(v1.x, v1.y), fmaxf(v1.z, v1.w)));
#pragma unroll
    for (int o = 16; o; o >>= 1) m = fmaxf(m, __shfl_xor_sync(0xffffffffu, m, o));
    if ((t & 31) == 0) red[t >> 5] = m;
    __syncthreads();
    float mm = red[0];
#pragma unroll
    for (int w = 1; w < 8; w++) mm = fmaxf(mm, red[w]);
    __syncthreads();
    float e[8];
    e[0] = __expf(v0.x - mm); e[1] = __expf(v0.y - mm);
    e[2] = __expf(v0.z - mm); e[3] = __expf(v0.w - mm);
    e[4] = __expf(v1.x - mm); e[5] = __expf(v1.y - mm);
    e[6] = __expf(v1.z - mm); e[7] = __expf(v1.w - mm);
    float s = 0.f;
#pragma unroll
    for (int i = 0; i < 8; i++) s += e[i];
#pragma unroll
    for (int o = 16; o; o >>= 1) s += __shfl_xor_sync(0xffffffffu, s, o);
    if ((t & 31) == 0) red[t >> 5] = s;
    __syncthreads();
    float tot = 0.f;
#pragma unroll
    for (int w = 0; w < 8; w++) tot += red[w];
    float inv = 1.f / tot;
    float4 o0, o1;
    o0.x = e[0]*inv; o0.y = e[1]*inv; o0.z = e[2]*inv; o0.w = e[3]*inv;
    o1.x = e[4]*inv; o1.y = e[5]*inv; o1.z = e[6]*inv; o1.w = e[7]*inv;
    *(float4*)&attn[base + t*4] = o0;
    *(float4*)&attn[base + 1024 + t*4] = o1;
}

// ---------------- AV: o = attn @ v (causal tile skip) ----------------
// 64-row x 64-col output tile per CTA, BK=64, 4x4 microtile.
#define AVP 68
__global__ void __launch_bounds__(256)
av_kernel(const float* __restrict__ attn) {
    __shared__ float Pt[64][AVP];   // transposed: Pt[j][r]
    __shared__ float Vs[64][AVP];   // Vs[j][d]
    int t = threadIdx.x;
    int h = blockIdx.y;
    int i0 = ((int)gridDim.x - 1 - (int)blockIdx.x) * 64;  // heavy tiles first
    const float* vh = g_v + (size_t)h*LQ*DHD;
    const float* ah = attn + ((size_t)h*LQ + i0)*LQ;

    int lr = t >> 2;            // 0..63
    int lc0 = (t & 3) * 16;

    int tx = t & 15, ty = t >> 4;
    float acc[4][4];
#pragma unroll
    for (int i = 0; i < 4; i++)
#pragma unroll
        for (int j = 0; j < 4; j++) acc[i][j] = 0.f;

    int numk = i0 + 64;
    for (int jc = 0; jc < numk; jc += 64) {
        __syncthreads();
        const float* arow = ah + (size_t)lr*LQ + jc + lc0;
#pragma unroll
        for (int c = 0; c < 4; c++) {
            float4 p = *(const float4*)(arow + c*4);
            Pt[lc0 + c*4 + 0][lr] = p.x;
            Pt[lc0 + c*4 + 1][lr] = p.y;
            Pt[lc0 + c*4 + 2][lr] = p.z;
            Pt[lc0 + c*4 + 3][lr] = p.w;
            float4 v = *(const float4*)(vh + (size_t)(jc + lr)*DHD + lc0 + c*4);
            *(float4*)&Vs[lr][lc0 + c*4] = v;
        }
        __syncthreads();
#pragma unroll 8
        for (int j = 0; j < 64; j++) {
            float a[4], b[4];
            *(float4*)a = *(const float4*)&Pt[j][ty*4];
            *(float4*)b = *(const float4*)&Vs[j][tx*4];
#pragma unroll
            for (int i = 0; i < 4; i++)
#pragma unroll
                for (int jj = 0; jj < 4; jj++)
                    acc[i][jj] += a[i] * b[jj];
        }
    }
#pragma unroll
    for (int i = 0; i < 4; i++) {
        float4 ov;
        ov.x = acc[i][0]; ov.y = acc[i][1]; ov.z = acc[i][2]; ov.w = acc[i][3];
        *(float4*)&g_o[(size_t)(i0 + ty*4 + i)*DD + h*DHD + tx*4] = ov;
    }
}

// ---------------- final: y = sigmoid(x@Wg+bg) * (o@Wo+bo) + x ----------------
__global__ void final_kernel(const float* __restrict__ x,
                             const float* __restrict__ bo,
                             const float* __restrict__ bg,
                             float* __restrict__ y) {
    int idx = blockIdx.x * 256 + threadIdx.x;
    int n = idx & (DD - 1);
    float yo = g_yo[idx] + bo[n];
    float gg = g_gg[idx] + bg[n];
    float gate = 1.f / (1.f + __expf(-gg));
    y[idx] = gate * yo + x[idx];
}

extern "C" void kernel_launch(void* const* d_in, const int* in_sizes, int n_in,
                              void* d_out, int out_size) {
    const float* x     = (const float*)d_in[0];
    const float* prev  = (const float*)d_in[1];
    const float* Wq    = (const float*)d_in[2];
    const float* Wk    = (const float*)d_in[3];
    const float* Wv    = (const float*)d_in[4];
    const float* Wo    = (const float*)d_in[5];
    const float* bo    = (const float*)d_in[6];
    const float* gamma = (const float*)d_in[7];
    const float* beta  = (const float*)d_in[8];
    const float* Wg    = (const float*)d_in[9];
    const float* bg    = (const float*)d_in[10];

    float* y    = (float*)d_out;
    float* attn = y + (size_t)LQ * DD;
    float* dots = attn + (size_t)NH * LQ * LQ;

    float *ph, *pq, *pk, *pv, *po, *pyo, *pgg;
    cudaGetSymbolAddress((void**)&ph,  g_h);
    cudaGetSymbolAddress((void**)&pq,  g_q);
    cudaGetSymbolAddress((void**)&pk,  g_k);
    cudaGetSymbolAddress((void**)&pv,  g_v);
    cudaGetSymbolAddress((void**)&po,  g_o);
    cudaGetSymbolAddress((void**)&pyo, g_yo);
    cudaGetSymbolAddress((void**)&pgg, g_gg);

    size_t qsmb = (size_t)(2*64*QKP) * sizeof(float);
    cudaFuncSetAttribute(qk_kernel, cudaFuncAttributeMaxDynamicSharedMemorySize, (int)qsmb);

    ln_kernel<<<LQ, 256>>>(x, gamma, beta);

    dim3 gg2(8, 16);
    sgemm_kernel<<<gg2, 256>>>(ph, Wq, pq, 1);
    sgemm_kernel<<<gg2, 256>>>(ph, Wk, pk, 1);
    sgemm_kernel<<<gg2, 256>>>(ph, Wv, pv, 1);

    rope_kernel<<<(NH*LQ*8)/256, 256>>>();

    qk_kernel<<<dim3(16, 16, 16), 256, qsmb>>>(prev, dots);
    softmax_kernel<<<NH*LQ, 256>>>(dots, attn);
    av_kernel<<<dim3(32, 16), 256>>>(attn);

    sgemm_kernel<<<gg2, 256>>>(po, Wo, pyo, 0);
    sgemm_kernel<<<gg2, 256>>>(x,  Wg, pgg, 0);

    final_kernel<<<(LQ*DD)/256, 256>>>(x, bo, bg, y);
}

// round 5
// speedup vs baseline: 3.2855x; 1.3860x over previous
#include <cuda_runtime.h>
#include <math.h>
#include <stdint.h>

#define LQ 2048
#define DD 1024
#define NH 16
#define DHD 64

__device__ float g_h [LQ*DD];
__device__ float g_q [NH*LQ*DHD];
__device__ float g_k [NH*LQ*DHD];
__device__ float g_v [NH*LQ*DHD];
__device__ float g_o [LQ*DD];
__device__ float g_yo[LQ*DD];
__device__ float g_gg[LQ*DD];

__device__ __forceinline__ uint32_t f2tf(float f) {
    uint32_t u;
    asm("cvt.rna.tf32.f32 %0, %1;" : "=r"(u) : "f"(f));
    return u;
}

__device__ __forceinline__ void mma8(float* c,
                                     uint32_t a0, uint32_t a1, uint32_t a2, uint32_t a3,
                                     uint32_t b0, uint32_t b1) {
    asm volatile("mma.sync.aligned.m16n8k8.row.col.f32.tf32.tf32.f32 "
        "{%0,%1,%2,%3}, {%4,%5,%6,%7}, {%8,%9}, {%0,%1,%2,%3};"
        : "+f"(c[0]), "+f"(c[1]), "+f"(c[2]), "+f"(c[3])
        : "r"(a0), "r"(a1), "r"(a2), "r"(a3), "r"(b0), "r"(b1));
}

// fragment-permuted position of k within an 8-deep k-step
#define POS(k) ((((k) & 3) * 2) + ((((k) >> 2) & 1)))

// ---------------- LayerNorm ----------------
__global__ void ln_kernel(const float* __restrict__ x,
                          const float* __restrict__ gamma,
                          const float* __restrict__ beta) {
    __shared__ float red[8];
    int row = blockIdx.x;
    int t = threadIdx.x;
    const float* xr = x + (size_t)row * DD;
    float v[4];
    float s = 0.f;
#pragma unroll
    for (int i = 0; i < 4; i++) { v[i] = xr[t + 256*i]; s += v[i]; }
#pragma unroll
    for (int o = 16; o; o >>= 1) s += __shfl_xor_sync(0xffffffffu, s, o);
    if ((t & 31) == 0) red[t >> 5] = s;
    __syncthreads();
    float tot = 0.f;
#pragma unroll
    for (int w = 0; w < 8; w++) tot += red[w];
    float mean = tot * (1.f / DD);
    __syncthreads();
    float s2 = 0.f;
#pragma unroll
    for (int i = 0; i < 4; i++) { float d = v[i] - mean; s2 += d*d; }
#pragma unroll
    for (int o = 16; o; o >>= 1) s2 += __shfl_xor_sync(0xffffffffu, s2, o);
    if ((t & 31) == 0) red[t >> 5] = s2;
    __syncthreads();
    float tot2 = 0.f;
#pragma unroll
    for (int w = 0; w < 8; w++) tot2 += red[w];
    float inv = rsqrtf(tot2 * (1.f / DD) + 1e-5f);
#pragma unroll
    for (int i = 0; i < 4; i++) {
        int c = t + 256*i;
        g_h[(size_t)row*DD + c] = (v[i] - mean) * inv * gamma[c] + beta[c];
    }
}

// ---------------- tf32 GEMM 128x128, kc=16, double-buffered ----------------
// C = A(2048x1024) @ B(1024x1024)
// mode 0: C[m*1024+n]   mode 1: head-major C[((n>>6)*LQ + m)*64 + (n&63)]
__global__ void __launch_bounds__(256)
gemm_tf32(const float* __restrict__ A, const float* __restrict__ B,
          float* __restrict__ C, int mode) {
    __shared__ uint32_t As[2][2][128*9];
    __shared__ uint32_t Bs[2][2][128*9];
    int t = threadIdx.x;
    int bm = blockIdx.y * 128, bn = blockIdx.x * 128;
    int lane = t & 31, wid = t >> 5;
    int g = lane >> 2, tg = lane & 3;
    int wm = (wid >> 2) * 64, wn = (wid & 3) * 32;

    int am = t & 127, akq = (t >> 7) * 8;      // A staging: row am, k-offset {0,8}
    int bk = t & 15,  bnq = (t >> 4) * 8;      // B staging: k-row bk, n-offset
    int pb = POS(bk), ksb = bk >> 3;

    const float* Ap = A + (size_t)(bm + am) * 1024 + akq;
    const float* Bp = B + (size_t)bk * 1024 + bn + bnq;

    float acc[4][4][4];
#pragma unroll
    for (int i = 0; i < 4; i++)
#pragma unroll
        for (int j = 0; j < 4; j++)
#pragma unroll
            for (int q = 0; q < 4; q++) acc[i][j][q] = 0.f;

    float4 a1v = *(const float4*)(Ap);
    float4 a2v = *(const float4*)(Ap + 4);
    float4 b1v = *(const float4*)(Bp);
    float4 b2v = *(const float4*)(Bp + 4);

#define STORE_TILE(BUF)                                                          \
    {                                                                            \
        const float* aa = (const float*)&a1v;                                    \
        _Pragma("unroll")                                                        \
        for (int e = 0; e < 4; e++) {                                            \
            int kk = akq + e;                                                    \
            As[BUF][kk >> 3][am * 9 + POS(kk)] = f2tf(aa[e]);                    \
        }                                                                        \
        const float* ab = (const float*)&a2v;                                    \
        _Pragma("unroll")                                                        \
        for (int e = 0; e < 4; e++) {                                            \
            int kk = akq + 4 + e;                                                \
            As[BUF][kk >> 3][am * 9 + POS(kk)] = f2tf(ab[e]);                    \
        }                                                                        \
        const float* ba = (const float*)&b1v;                                    \
        _Pragma("unroll")                                                        \
        for (int e = 0; e < 4; e++)                                              \
            Bs[BUF][ksb][(bnq + e) * 9 + pb] = f2tf(ba[e]);                      \
        const float* bb = (const float*)&b2v;                                    \
        _Pragma("unroll")                                                        \
        for (int e = 0; e < 4; e++)                                              \
            Bs[BUF][ksb][(bnq + 4 + e) * 9 + pb] = f2tf(bb[e]);                  \
    }

#define COMPUTE(BUF)                                                             \
    {                                                                            \
        _Pragma("unroll")                                                        \
        for (int ks = 0; ks < 2; ks++) {                                         \
            uint32_t af[4][4];                                                   \
            uint32_t bf[4][2];                                                   \
            _Pragma("unroll")                                                    \
            for (int mt = 0; mt < 4; mt++) {                                     \
                const uint32_t* pa = &As[BUF][ks][(wm + mt*16 + g)*9 + 2*tg];    \
                const uint32_t* pa2 = &As[BUF][ks][(wm + mt*16 + g + 8)*9 + 2*tg];\
                af[mt][0] = pa[0]; af[mt][1] = pa2[0];                           \
                af[mt][2] = pa[1]; af[mt][3] = pa2[1];                           \
            }                                                                    \
            _Pragma("unroll")                                                    \
            for (int nt = 0; nt < 4; nt++) {                                     \
                const uint32_t* pbp = &Bs[BUF][ks][(wn + nt*8 + g)*9 + 2*tg];    \
                bf[nt][0] = pbp[0]; bf[nt][1] = pbp[1];                          \
            }                                                                    \
            _Pragma("unroll")                                                    \
            for (int mt = 0; mt < 4; mt++)                                       \
                _Pragma("unroll")                                                \
                for (int nt = 0; nt < 4; nt++)                                   \
                    mma8(acc[mt][nt], af[mt][0], af[mt][1], af[mt][2], af[mt][3],\
                         bf[nt][0], bf[nt][1]);                                  \
        }                                                                        \
    }

    STORE_TILE(0);
    __syncthreads();
    int buf = 0;
    for (int k0 = 16; k0 < 1024; k0 += 16) {
        a1v = *(const float4*)(Ap + k0);
        a2v = *(const float4*)(Ap + k0 + 4);
        b1v = *(const float4*)(Bp + (size_t)k0 * 1024);
        b2v = *(const float4*)(Bp + (size_t)k0 * 1024 + 4);
        COMPUTE(buf);
        buf ^= 1;
        STORE_TILE(buf);
        __syncthreads();
    }
    COMPUTE(buf);

#pragma unroll
    for (int mt = 0; mt < 4; mt++) {
#pragma unroll
        for (int nt = 0; nt < 4; nt++) {
            int m = bm + wm + mt*16 + g;
            int n = bn + wn + nt*8 + 2*tg;
            float2 v0 = make_float2(acc[mt][nt][0], acc[mt][nt][1]);
            float2 v1 = make_float2(acc[mt][nt][2], acc[mt][nt][3]);
            if (mode == 0) {
                *(float2*)&C[(size_t)m*1024 + n] = v0;
                *(float2*)&C[(size_t)(m+8)*1024 + n] = v1;
            } else {
                size_t b0i = ((size_t)(n >> 6)*LQ + m)*DHD + (n & 63);
                size_t b1i = ((size_t)(n >> 6)*LQ + m + 8)*DHD + (n & 63);
                *(float2*)&C[b0i] = v0;
                *(float2*)&C[b1i] = v1;
            }
        }
    }
#undef STORE_TILE
#undef COMPUTE
}

// ---------------- RoPE on q,k,v ----------------
__global__ void rope_kernel() {
    int idx = blockIdx.x * blockDim.x + threadIdx.x;   // NH*LQ*8
    int pair = idx & 7;
    int rest = idx >> 3;
    int l = rest & (LQ - 1);
    int base = rest * DHD;
    float invf = powf(10000.f, -(float)pair * 0.125f);
    float ang = (float)l * invf;
    float s, c;
    sincosf(ang, &s, &c);
    float a, b;
    a = g_q[base + pair]; b = g_q[base + pair + 8];
    g_q[base + pair] = a*c - b*s; g_q[base + pair + 8] = b*c + a*s;
    a = g_k[base + pair]; b = g_k[base + pair + 8];
    g_k[base + pair] = a*c - b*s; g_k[base + pair + 8] = b*c + a*s;
    a = g_v[base + pair]; b = g_v[base + pair + 8];
    g_v[base + pair] = a*c - b*s; g_v[base + pair + 8] = b*c + a*s;
}

// ---------------- QK tf32: dots = q@k^T*scale + prev + alibi/causal ----------------
// 128x128 tile, full K=64 in one pass. Q,K staged fragment-permuted tf32.
__global__ void __launch_bounds__(256)
qk_tf32(const float* __restrict__ prev, float* __restrict__ dots) {
    extern __shared__ uint32_t sm[];
    uint32_t* Qs = sm;              // [8][128*9]
    uint32_t* Ks = sm + 8*1152;
    int t = threadIdx.x;
    int h = blockIdx.z;
    int i0 = blockIdx.y * 128, j0 = blockIdx.x * 128;
    int lane = t & 31, wid = t >> 5;
    int g = lane >> 2, tg = lane & 3;
    int wm = (wid >> 2) * 64, wn = (wid & 3) * 32;

    const float* qh = g_q + (size_t)h*LQ*DHD;
    const float* kh = g_k + (size_t)h*LQ*DHD;

    int m = t & 127, half = t >> 7, hk = half * 32;
    const float* qrow = qh + (size_t)(i0 + m)*DHD + hk;
    const float* krow = kh + (size_t)(j0 + m)*DHD + hk;
#pragma unroll
    for (int q = 0; q < 8; q++) {
        float4 v = *(const float4*)(qrow + q*4);
        float4 w = *(const float4*)(krow + q*4);
        const float* vp = (const float*)&v;
        const float* wp = (const float*)&w;
#pragma unroll
        for (int e = 0; e < 4; e++) {
            int kk = hk + q*4 + e;
            Qs[(kk >> 3)*1152 + m*9 + POS(kk)] = f2tf(vp[e]);
            Ks[(kk >> 3)*1152 + m*9 + POS(kk)] = f2tf(wp[e]);
        }
    }
    __syncthreads();

    float acc[4][4][4];
#pragma unroll
    for (int i = 0; i < 4; i++)
#pragma unroll
        for (int j = 0; j < 4; j++)
#pragma unroll
            for (int q = 0; q < 4; q++) acc[i][j][q] = 0.f;

#pragma unroll
    for (int ks = 0; ks < 8; ks++) {
        uint32_t af[4][4];
        uint32_t bf[4][2];
#pragma unroll
        for (int mt = 0; mt < 4; mt++) {
            const uint32_t* pa  = &Qs[ks*1152 + (wm + mt*16 + g)*9 + 2*tg];
            const uint32_t* pa2 = &Qs[ks*1152 + (wm + mt*16 + g + 8)*9 + 2*tg];
            af[mt][0] = pa[0]; af[mt][1] = pa2[0];
            af[mt][2] = pa[1]; af[mt][3] = pa2[1];
        }
#pragma unroll
        for (int nt = 0; nt < 4; nt++) {
            const uint32_t* pbp = &Ks[ks*1152 + (wn + nt*8 + g)*9 + 2*tg];
            bf[nt][0] = pbp[0]; bf[nt][1] = pbp[1];
        }
#pragma unroll
        for (int mt = 0; mt < 4; mt++)
#pragma unroll
            for (int nt = 0; nt < 4; nt++)
                mma8(acc[mt][nt], af[mt][0], af[mt][1], af[mt][2], af[mt][3],
                     bf[nt][0], bf[nt][1]);
    }

    float slope = exp2f(-0.5f * (float)(h + 1));
#pragma unroll
    for (int mt = 0; mt < 4; mt++) {
#pragma unroll
        for (int nt = 0; nt < 4; nt++) {
            int j = j0 + wn + nt*8 + 2*tg;
#pragma unroll
            for (int rr = 0; rr < 2; rr++) {
                int gi = i0 + wm + mt*16 + g + rr*8;
                size_t rowb = ((size_t)(h*LQ + gi))*LQ;
                float2 pv = *(const float2*)&prev[rowb + j];
                int rel0 = gi - j, rel1 = gi - (j + 1);
                float2 ov;
                ov.x = acc[mt][nt][rr*2+0]*0.125f + pv.x +
                       ((rel0 >= 0) ? (-slope*(float)rel0) : -1000000000.0f);
                ov.y = acc[mt][nt][rr*2+1]*0.125f + pv.y +
                       ((rel1 >= 0) ? (-slope*(float)rel1) : -1000000000.0f);
                *(float2*)&dots[rowb + j] = ov;
            }
        }
    }
}

// ---------------- softmax per row ----------------
__global__ void __launch_bounds__(256)
softmax_kernel(const float* __restrict__ dots, float* __restrict__ attn) {
    __shared__ float red[8];
    size_t base = (size_t)blockIdx.x * LQ;
    int t = threadIdx.x;
    float4 v0 = *(const float4*)&dots[base + t*4];
    float4 v1 = *(const float4*)&dots[base + 1024 + t*4];
    float m = fmaxf(fmaxf(fmaxf(v0.x, v0.y), fmaxf(v0.z, v0.w)),
                    fmaxf(fmaxf(v1.x, v1.y), fmaxf(v1.z, v1.w)));
#pragma unroll
    for (int o = 16; o; o >>= 1) m = fmaxf(m, __shfl_xor_sync(0xffffffffu, m, o));
    if ((t & 31) == 0) red[t >> 5] = m;
    __syncthreads();
    float mm = red[0];
#pragma unroll
    for (int w = 1; w < 8; w++) mm = fmaxf(mm, red[w]);
    __syncthreads();
    float e[8];
    e[0] = __expf(v0.x - mm); e[1] = __expf(v0.y - mm);
    e[2] = __expf(v0.z - mm); e[3] = __expf(v0.w - mm);
    e[4] = __expf(v1.x - mm); e[5] = __expf(v1.y - mm);
    e[6] = __expf(v1.z - mm); e[7] = __expf(v1.w - mm);
    float s = 0.f;
#pragma unroll
    for (int i = 0; i < 8; i++) s += e[i];
#pragma unroll
    for (int o = 16; o; o >>= 1) s += __shfl_xor_sync(0xffffffffu, s, o);
    if ((t & 31) == 0) red[t >> 5] = s;
    __syncthreads();
    float tot = 0.f;
#pragma unroll
    for (int w = 0; w < 8; w++) tot += red[w];
    float inv = 1.f / tot;
    float4 o0, o1;
    o0.x = e[0]*inv; o0.y = e[1]*inv; o0.z = e[2]*inv; o0.w = e[3]*inv;
    o1.x = e[4]*inv; o1.y = e[5]*inv; o1.z = e[6]*inv; o1.w = e[7]*inv;
    *(float4*)&attn[base + t*4] = o0;
    *(float4*)&attn[base + 1024 + t*4] = o1;
}

// ---------------- AV tf32: o = attn @ v, causal chunk skip ----------------
// 64(i) x 64(d) tile, k-chunks of 64.
__global__ void __launch_bounds__(256)
av_tf32(const float* __restrict__ attn) {
    __shared__ uint32_t As[8][64*9];
    __shared__ uint32_t Vs[8][64*9];
    int t = threadIdx.x;
    int h = blockIdx.y;
    int i0 = ((int)gridDim.x - 1 - (int)blockIdx.x) * 64;   // heavy tiles first
    int lane = t & 31, wid = t >> 5;
    int g = lane >> 2, tg = lane & 3;
    int wm = (wid >> 1) * 16, wn = (wid & 1) * 32;

    const float* vh = g_v + (size_t)h*LQ*DHD;
    const float* ah = attn + ((size_t)h*LQ + i0)*LQ;

    int am = t & 63, akq = (t >> 6) * 16;   // attn: row am, k in [akq, akq+16)
    int vk = t >> 2, vnq = (t & 3) * 16;    // V: k-row vk, n in [vnq, vnq+16)
    int pvp = POS(vk), ksv = vk >> 3;

    float acc[4][4];
#pragma unroll
    for (int i = 0; i < 4; i++)
#pragma unroll
        for (int j = 0; j < 4; j++) acc[i][j] = 0.f;

    for (int jc = 0; jc <= i0; jc += 64) {
        __syncthreads();
        const float* ar = ah + (size_t)am*LQ + jc + akq;
        const float* vr = vh + (size_t)(jc + vk)*DHD + vnq;
#pragma unroll
        for (int q = 0; q < 4; q++) {
            float4 v = *(const float4*)(ar + q*4);
            float4 w = *(const float4*)(vr + q*4);
            const float* vp = (const float*)&v;
            const float* wp = (const float*)&w;
#pragma unroll
            for (int e = 0; e < 4; e++) {
                int kk = akq + q*4 + e;
                As[kk >> 3][am*9 + POS(kk)] = f2tf(vp[e]);
                int n = vnq + q*4 + e;
                Vs[ksv][n*9 + pvp] = f2tf(wp[e]);
            }
        }
        __syncthreads();
#pragma unroll
        for (int ks = 0; ks < 8; ks++) {
            const uint32_t* pa  = &As[ks][(wm + g)*9 + 2*tg];
            const uint32_t* pa2 = &As[ks][(wm + g + 8)*9 + 2*tg];
            uint32_t a0 = pa[0], a1 = pa2[0], a2 = pa[1], a3 = pa2[1];
#pragma unroll
            for (int nt = 0; nt < 4; nt++) {
                const uint32_t* pbp = &Vs[ks][(wn + nt*8 + g)*9 + 2*tg];
                mma8(acc[nt], a0, a1, a2, a3, pbp[0], pbp[1]);
            }
        }
    }

#pragma unroll
    for (int nt = 0; nt < 4; nt++) {
        int d = wn + nt*8 + 2*tg;
        int i = i0 + wm + g;
        *(float2*)&g_o[(size_t)i*DD + h*DHD + d] =
            make_float2(acc[nt][0], acc[nt][1]);
        *(float2*)&g_o[(size_t)(i+8)*DD + h*DHD + d] =
            make_float2(acc[nt][2], acc[nt][3]);
    }
}

// ---------------- final: y = sigmoid(x@Wg+bg) * (o@Wo+bo) + x ----------------
__global__ void final_kernel(const float* __restrict__ x,
                             const float* __restrict__ bo,
                             const float* __restrict__ bg,
                             float* __restrict__ y) {
    int idx = blockIdx.x * 256 + threadIdx.x;
    int n = idx & (DD - 1);
    float yo = g_yo[idx] + bo[n];
    float gg = g_gg[idx] + bg[n];
    float gate = 1.f / (1.f + __expf(-gg));
    y[idx] = gate * yo + x[idx];
}

extern "C" void kernel_launch(void* const* d_in, const int* in_sizes, int n_in,
                              void* d_out, int out_size) {
    const float* x     = (const float*)d_in[0];
    const float* prev  = (const float*)d_in[1];
    const float* Wq    = (const float*)d_in[2];
    const float* Wk    = (const float*)d_in[3];
    const float* Wv    = (const float*)d_in[4];
    const float* Wo    = (const float*)d_in[5];
    const float* bo    = (const float*)d_in[6];
    const float* gamma = (const float*)d_in[7];
    const float* beta  = (const float*)d_in[8];
    const float* Wg    = (const float*)d_in[9];
    const float* bg    = (const float*)d_in[10];

    float* y    = (float*)d_out;
    float* attn = y + (size_t)LQ * DD;
    float* dots = attn + (size_t)NH * LQ * LQ;

    float *ph, *pq, *pk, *pv, *po, *pyo, *pgg;
    cudaGetSymbolAddress((void**)&ph,  g_h);
    cudaGetSymbolAddress((void**)&pq,  g_q);
    cudaGetSymbolAddress((void**)&pk,  g_k);
    cudaGetSymbolAddress((void**)&pv,  g_v);
    cudaGetSymbolAddress((void**)&po,  g_o);
    cudaGetSymbolAddress((void**)&pyo, g_yo);
    cudaGetSymbolAddress((void**)&pgg, g_gg);

    size_t qsmb = (size_t)(2 * 8 * 1152) * sizeof(uint32_t);
    cudaFuncSetAttribute(qk_tf32, cudaFuncAttributeMaxDynamicSharedMemorySize, (int)qsmb);

    ln_kernel<<<LQ, 256>>>(x, gamma, beta);

    dim3 gg2(8, 16);
    gemm_tf32<<<gg2, 256>>>(ph, Wq, pq, 1);
    gemm_tf32<<<gg2, 256>>>(ph, Wk, pk, 1);
    gemm_tf32<<<gg2, 256>>>(ph, Wv, pv, 1);

    rope_kernel<<<(NH*LQ*8)/256, 256>>>();

    qk_tf32<<<dim3(16, 16, 16), 256, qsmb>>>(prev, dots);
    softmax_kernel<<<NH*LQ, 256>>>(dots, attn);
    av_tf32<<<dim3(32, 16), 256>>>(attn);

    gemm_tf32<<<gg2, 256>>>(po, Wo, pyo, 0);
    gemm_tf32<<<gg2, 256>>>(x,  Wg, pgg, 0);

    final_kernel<<<(LQ*DD)/256, 256>>>(x, bo, bg, y);
}